// round 3
// baseline (speedup 1.0000x reference)
#include <cuda_runtime.h>
#include <math.h>
#include <stdint.h>

#define E_DIM 1024
#define B_DIM 8192
#define NROWS (B_DIM * 2)          // 16384
#define HID 2048

// ---------------- scratch (device globals; no allocations allowed) ----------
__device__ float g_xs[(size_t)NROWS * E_DIM];   // ln1 output
__device__ float g_q [(size_t)NROWS * E_DIM];
__device__ float g_k [(size_t)NROWS * E_DIM];
__device__ float g_v [(size_t)NROWS * E_DIM];
__device__ float g_cc[(size_t)NROWS * E_DIM];   // attention concat
__device__ float g_o1[(size_t)NROWS * E_DIM];   // input + res
__device__ float g_os[(size_t)NROWS * E_DIM];   // ln2 output
__device__ float g_h [(size_t)B_DIM * HID];     // ffn hidden (reused s=0,1)

// ---------------- LayerNorm over joint (S=2, E=1024) = 2048 elems ----------
__global__ void ln_kernel(const float* __restrict__ x, const float* __restrict__ w,
                          const float* __restrict__ bb, float* __restrict__ y) {
    int b = blockIdx.x;
    int tid = threadIdx.x;
    const float* xr = x + (size_t)b * 2048;
    float v[8];
    float s = 0.f, s2 = 0.f;
#pragma unroll
    for (int i = 0; i < 8; i++) {
        float t = xr[tid + 256 * i];
        v[i] = t; s += t; s2 += t * t;
    }
#pragma unroll
    for (int o = 16; o; o >>= 1) {
        s  += __shfl_xor_sync(0xFFFFFFFFu, s,  o);
        s2 += __shfl_xor_sync(0xFFFFFFFFu, s2, o);
    }
    __shared__ float rs[8], rs2[8];
    __shared__ float mean_s, rstd_s;
    if ((tid & 31) == 0) { rs[tid >> 5] = s; rs2[tid >> 5] = s2; }
    __syncthreads();
    if (tid == 0) {
        float a = 0.f, a2 = 0.f;
#pragma unroll
        for (int i = 0; i < 8; i++) { a += rs[i]; a2 += rs2[i]; }
        float m = a * (1.f / 2048.f);
        float var = a2 * (1.f / 2048.f) - m * m;
        mean_s = m;
        rstd_s = rsqrtf(var + 1e-5f);
    }
    __syncthreads();
    float m = mean_s, r = rstd_s;
    float* yr = y + (size_t)b * 2048;
#pragma unroll
    for (int i = 0; i < 8; i++) {
        int j = tid + 256 * i;
        yr[j] = (v[i] - m) * r * w[j] + bb[j];
    }
}

// ---------------- Attention (S=2, H=16, NH=64), writes concat layout -------
// q[b,h,s,d] = Q[(2b+s)*1024 + d*16 + h];  concat[(2b+s)*1024 + d*16+h] = out
__global__ void attn_kernel(const float* __restrict__ Q, const float* __restrict__ K,
                            const float* __restrict__ V, float* __restrict__ O) {
    int b = blockIdx.x;
    int tid = threadIdx.x;
    __shared__ float sQ[2048], sK[2048];
    __shared__ float part[256 * 4];
    __shared__ float sp[4 * 16];    // [(s*2+t)*16 + h]
    const float* qp = Q + (size_t)b * 2048;
    const float* kp = K + (size_t)b * 2048;
#pragma unroll
    for (int i = 0; i < 8; i++) {
        sQ[tid + 256 * i] = qp[tid + 256 * i];
        sK[tid + 256 * i] = kp[tid + 256 * i];
    }
    __syncthreads();
    int h = tid & 15, u = tid >> 4;
    float p00 = 0.f, p01 = 0.f, p10 = 0.f, p11 = 0.f;
#pragma unroll
    for (int i = 0; i < 4; i++) {
        int j = h + 16 * u + 256 * i;     // columns with j%16 == h
        float q0 = sQ[j], q1 = sQ[1024 + j];
        float k0 = sK[j], k1 = sK[1024 + j];
        p00 += q0 * k0; p01 += q0 * k1;
        p10 += q1 * k0; p11 += q1 * k1;
    }
    part[tid * 4 + 0] = p00; part[tid * 4 + 1] = p01;
    part[tid * 4 + 2] = p10; part[tid * 4 + 3] = p11;
    __syncthreads();
    if (tid < 32) {
        int s = tid >> 4;
        int hh = tid & 15;
        float a0 = 0.f, a1 = 0.f;
#pragma unroll
        for (int uu = 0; uu < 16; uu++) {
            a0 += part[(uu * 16 + hh) * 4 + s * 2 + 0];
            a1 += part[(uu * 16 + hh) * 4 + s * 2 + 1];
        }
        a0 *= 0.125f; a1 *= 0.125f;           // / sqrt(64)
        float mx = fmaxf(a0, a1);
        float e0 = expf(a0 - mx), e1 = expf(a1 - mx);
        float inv = 1.f / (e0 + e1);
        sp[(s * 2 + 0) * 16 + hh] = e0 * inv;
        sp[(s * 2 + 1) * 16 + hh] = e1 * inv;
    }
    __syncthreads();
    const float* vp = V + (size_t)b * 2048;
    float* op = O + (size_t)b * 2048;
#pragma unroll
    for (int i = 0; i < 4; i++) {
        int j = tid + 256 * i;
        int hh = j & 15;
        float v0 = vp[j], v1 = vp[1024 + j];
        op[j]        = sp[0 * 16 + hh] * v0 + sp[1 * 16 + hh] * v1;
        op[1024 + j] = sp[2 * 16 + hh] * v0 + sp[3 * 16 + hh] * v1;
    }
}

// ---------------- TF32 tensor-core GEMM: C[m,n] = sum_k A[m,k]*W[n,k] -------
#define BM 128
#define BN 128
#define BK 32
#define SROW 36                        // row stride in floats: conflict-free frag loads
#define STAGE_F (BM * SROW)            // 4608 floats / tile / stage
#define SMEM_BYTES (4 * STAGE_F * 4)   // A(2 stages) + B(2 stages) = 73728 B

__device__ __forceinline__ void cpa16(float* sdst, const float* g) {
    uint32_t s = (uint32_t)__cvta_generic_to_shared(sdst);
    asm volatile("cp.async.cg.shared.global [%0], [%1], 16;\n" :: "r"(s), "l"(g));
}
__device__ __forceinline__ uint32_t f2tf(float f) {
    uint32_t r;
    asm volatile("cvt.rna.tf32.f32 %0, %1;" : "=r"(r) : "f"(f));
    return r;
}
__device__ __forceinline__ void mma8(float* d, const uint32_t* a, const uint32_t* b2) {
    asm volatile(
        "mma.sync.aligned.m16n8k8.row.col.f32.tf32.tf32.f32 "
        "{%0,%1,%2,%3}, {%4,%5,%6,%7}, {%8,%9}, {%0,%1,%2,%3};\n"
        : "+f"(d[0]), "+f"(d[1]), "+f"(d[2]), "+f"(d[3])
        : "r"(a[0]), "r"(a[1]), "r"(a[2]), "r"(a[3]), "r"(b2[0]), "r"(b2[1]));
}

__global__ __launch_bounds__(256, 2) void gemm_tf32(
    const float* __restrict__ A, long lda,        // M x K (row-major, row stride lda)
    const float* __restrict__ W, long ldw,        // N x K (row-major, row stride ldw)
    const float* __restrict__ bias,               // [N] or null
    const float* __restrict__ resid, long ldr,    // residual add or null
    float* __restrict__ C, long ldc,
    int K, int doTanh)
{
    extern __shared__ float smem[];
    float* sA = smem;                  // [2][BM][SROW]
    float* sB = smem + 2 * STAGE_F;    // [2][BN][SROW]
    int tid = threadIdx.x;
    int warp = tid >> 5, lane = tid & 31;
    int wm = warp >> 2, wn = warp & 3;             // warp grid 2(M) x 4(N), warp tile 64x32
    long bm = (long)blockIdx.y * BM;
    long bn = (long)blockIdx.x * BN;
    int lrow = tid >> 3;                            // 0..31
    int lcol = (tid & 7) * 4;                       // 0..28
    const float* Abase = A + (bm + lrow) * lda + lcol;
    const float* Wbase = W + (bn + lrow) * ldw + lcol;

    float acc[4][4][4];
#pragma unroll
    for (int i = 0; i < 4; i++)
#pragma unroll
        for (int j = 0; j < 4; j++)
#pragma unroll
            for (int q = 0; q < 4; q++) acc[i][j][q] = 0.f;

    int nk = K / BK;
    {   // prologue: stage 0
#pragma unroll
        for (int i = 0; i < 4; i++) {
            cpa16(&sA[(lrow + 32 * i) * SROW + lcol], Abase + (long)(32 * i) * lda);
            cpa16(&sB[(lrow + 32 * i) * SROW + lcol], Wbase + (long)(32 * i) * ldw);
        }
        asm volatile("cp.async.commit_group;\n");
    }
    for (int kt = 0; kt < nk; kt++) {
        if (kt + 1 < nk) {
            int stg = (kt + 1) & 1;
            float* dA = sA + stg * STAGE_F;
            float* dB = sB + stg * STAGE_F;
            long ko = (long)(kt + 1) * BK;
#pragma unroll
            for (int i = 0; i < 4; i++) {
                cpa16(&dA[(lrow + 32 * i) * SROW + lcol], Abase + (long)(32 * i) * lda + ko);
                cpa16(&dB[(lrow + 32 * i) * SROW + lcol], Wbase + (long)(32 * i) * ldw + ko);
            }
        }
        asm volatile("cp.async.commit_group;\n");
        asm volatile("cp.async.wait_group 1;\n");
        __syncthreads();
        const float* aS = sA + (kt & 1) * STAGE_F;
        const float* bS = sB + (kt & 1) * STAGE_F;
#pragma unroll
        for (int kk = 0; kk < BK; kk += 8) {
            uint32_t af[4][4], bf[4][2];
            int rA = wm * 64 + (lane >> 2);
            int cK = kk + (lane & 3);
#pragma unroll
            for (int mt = 0; mt < 4; mt++) {
                const float* p = aS + (rA + mt * 16) * SROW + cK;
                af[mt][0] = f2tf(p[0]);
                af[mt][1] = f2tf(p[8 * SROW]);
                af[mt][2] = f2tf(p[4]);
                af[mt][3] = f2tf(p[8 * SROW + 4]);
            }
            int rB = wn * 32 + (lane >> 2);
#pragma unroll
            for (int nt = 0; nt < 4; nt++) {
                const float* p = bS + (rB + nt * 8) * SROW + cK;
                bf[nt][0] = f2tf(p[0]);
                bf[nt][1] = f2tf(p[4]);
            }
#pragma unroll
            for (int mt = 0; mt < 4; mt++)
#pragma unroll
                for (int nt = 0; nt < 4; nt++)
                    mma8(acc[mt][nt], af[mt], bf[nt]);
        }
        __syncthreads();
    }
    // epilogue: bias -> tanh -> residual
#pragma unroll
    for (int mt = 0; mt < 4; mt++) {
        long row0 = bm + wm * 64 + mt * 16 + (lane >> 2);
#pragma unroll
        for (int nt = 0; nt < 4; nt++) {
            long col = bn + wn * 32 + nt * 8 + (lane & 3) * 2;
#pragma unroll
            for (int hh = 0; hh < 2; hh++) {
                long row = row0 + hh * 8;
                float x0 = acc[mt][nt][hh * 2 + 0];
                float x1 = acc[mt][nt][hh * 2 + 1];
                if (bias) { x0 += bias[col]; x1 += bias[col + 1]; }
                if (doTanh) { x0 = tanhf(x0); x1 = tanhf(x1); }
                if (resid) {
                    const float* rp = resid + row * ldr + col;
                    x0 += rp[0]; x1 += rp[1];
                }
                float2 o; o.x = x0; o.y = x1;
                *reinterpret_cast<float2*>(C + row * ldc + col) = o;
            }
        }
    }
}

// ---------------- host launch ------------------------------------------------
static float* symaddr(const void* s) {
    void* p = nullptr;
    cudaGetSymbolAddress(&p, s);
    return (float*)p;
}

extern "C" void kernel_launch(void* const* d_in, const int* in_sizes, int n_in,
                              void* d_out, int out_size) {
    const float* input = (const float*)d_in[0];
    const float* Wq    = (const float*)d_in[1];
    const float* Wk    = (const float*)d_in[2];
    const float* Wv    = (const float*)d_in[3];
    const float* Wo    = (const float*)d_in[4];
    const float* ln1w  = (const float*)d_in[5];
    const float* ln1b  = (const float*)d_in[6];
    const float* ln2w  = (const float*)d_in[7];
    const float* ln2b  = (const float*)d_in[8];
    const float* f1w1  = (const float*)d_in[9];
    const float* f1b1  = (const float*)d_in[10];
    const float* f1w2  = (const float*)d_in[11];
    const float* f1b2  = (const float*)d_in[12];
    const float* f2w1  = (const float*)d_in[13];
    const float* f2b1  = (const float*)d_in[14];
    const float* f2w2  = (const float*)d_in[15];
    const float* f2b2  = (const float*)d_in[16];
    float* out = (float*)d_out;

    float* xs = symaddr(g_xs);
    float* q  = symaddr(g_q);
    float* k  = symaddr(g_k);
    float* v  = symaddr(g_v);
    float* cc = symaddr(g_cc);
    float* o1 = symaddr(g_o1);
    float* os = symaddr(g_os);
    float* hd = symaddr(g_h);

    cudaFuncSetAttribute(gemm_tf32, cudaFuncAttributeMaxDynamicSharedMemorySize, SMEM_BYTES);

    // 1) LN1
    ln_kernel<<<B_DIM, 256>>>(input, ln1w, ln1b, xs);

    // 2) Q/K/V projections
    dim3 gq(E_DIM / BN, NROWS / BM);   // (8, 128)
    gemm_tf32<<<gq, 256, SMEM_BYTES>>>(xs, E_DIM, Wq, E_DIM, nullptr, nullptr, 0, q, E_DIM, E_DIM, 0);
    gemm_tf32<<<gq, 256, SMEM_BYTES>>>(xs, E_DIM, Wk, E_DIM, nullptr, nullptr, 0, k, E_DIM, E_DIM, 0);
    gemm_tf32<<<gq, 256, SMEM_BYTES>>>(xs, E_DIM, Wv, E_DIM, nullptr, nullptr, 0, v, E_DIM, E_DIM, 0);

    // 3) attention -> concat
    attn_kernel<<<B_DIM, 256>>>(q, k, v, cc);

    // 4) Wo projection, fused residual: o1 = input + concat @ Wo^T
    gemm_tf32<<<gq, 256, SMEM_BYTES>>>(cc, E_DIM, Wo, E_DIM, nullptr, input, E_DIM, o1, E_DIM, E_DIM, 0);

    // 5) LN2
    ln_kernel<<<B_DIM, 256>>>(o1, ln2w, ln2b, os);

    // 6) FFN s=0: hd = tanh(os0 @ f1w1^T + b); out0 = tanh(hd @ f1w2^T + b) + o1_0
    dim3 gf1(HID / BN, B_DIM / BM);    // (16, 64)
    dim3 gf2(E_DIM / BN, B_DIM / BM);  // (8, 64)
    gemm_tf32<<<gf1, 256, SMEM_BYTES>>>(os,        HID, f1w1, E_DIM, f1b1, nullptr, 0,   hd,  HID,  E_DIM, 1);
    gemm_tf32<<<gf2, 256, SMEM_BYTES>>>(hd,        HID, f1w2, HID,   f1b2, o1,      HID, out, HID,  HID,   1);
    // 7) FFN s=1
    gemm_tf32<<<gf1, 256, SMEM_BYTES>>>(os + 1024, HID, f2w1, E_DIM, f2b1, nullptr, 0,   hd,        HID, E_DIM, 1);
    gemm_tf32<<<gf2, 256, SMEM_BYTES>>>(hd,        HID, f2w2, HID,   f2b2, o1 + 1024, HID, out + 1024, HID, HID, 1);
}

// round 6
// speedup vs baseline: 1.0191x; 1.0191x over previous
#include <cuda_runtime.h>
#include <math.h>
#include <stdint.h>

#define E_DIM 1024
#define B_DIM 8192
#define NROWS (B_DIM * 2)          // 16384
#define HID 2048

// ---------------- scratch (device globals; no allocations allowed) ----------
__device__ float g_xs[(size_t)NROWS * E_DIM];   // ln1 output (tf32-rounded)
__device__ float g_q [(size_t)NROWS * E_DIM];
__device__ float g_k [(size_t)NROWS * E_DIM];
__device__ float g_v [(size_t)NROWS * E_DIM];
__device__ float g_cc[(size_t)NROWS * E_DIM];   // attention concat (tf32-rounded)
__device__ float g_o1[(size_t)NROWS * E_DIM];   // input + res (full fp32)
__device__ float g_os[(size_t)NROWS * E_DIM];   // ln2 output (tf32-rounded)
__device__ float g_h [(size_t)B_DIM * HID];     // ffn hidden (tf32-rounded)
__device__ float g_wr[(size_t)12 * 1024 * 1024]; // tf32-rounded weights

__device__ __forceinline__ uint32_t f2tf(float f) {
    uint32_t r;
    asm volatile("cvt.rna.tf32.f32 %0, %1;" : "=r"(r) : "f"(f));
    return r;
}
__device__ __forceinline__ float rtf(float f) { return __uint_as_float(f2tf(f)); }

// ---------------- weight rounding (fp32 -> tf32 bit pattern) ----------------
__global__ void round_w(const float* __restrict__ src, float* __restrict__ dst, int n) {
    int i = blockIdx.x * 1024 + threadIdx.x;
    if (i < n) dst[i] = rtf(src[i]);
}

// ---------------- LayerNorm over joint (S=2, E=1024) = 2048 elems ----------
__global__ void ln_kernel(const float* __restrict__ x, const float* __restrict__ w,
                          const float* __restrict__ bb, float* __restrict__ y) {
    int b = blockIdx.x;
    int tid = threadIdx.x;
    const float* xr = x + (size_t)b * 2048;
    float v[8];
    float s = 0.f, s2 = 0.f;
#pragma unroll
    for (int i = 0; i < 8; i++) {
        float t = xr[tid + 256 * i];
        v[i] = t; s += t; s2 += t * t;
    }
#pragma unroll
    for (int o = 16; o; o >>= 1) {
        s  += __shfl_xor_sync(0xFFFFFFFFu, s,  o);
        s2 += __shfl_xor_sync(0xFFFFFFFFu, s2, o);
    }
    __shared__ float rs[8], rs2[8];
    __shared__ float mean_s, rstd_s;
    if ((tid & 31) == 0) { rs[tid >> 5] = s; rs2[tid >> 5] = s2; }
    __syncthreads();
    if (tid == 0) {
        float a = 0.f, a2 = 0.f;
#pragma unroll
        for (int i = 0; i < 8; i++) { a += rs[i]; a2 += rs2[i]; }
        float m = a * (1.f / 2048.f);
        float var = a2 * (1.f / 2048.f) - m * m;
        mean_s = m;
        rstd_s = rsqrtf(var + 1e-5f);
    }
    __syncthreads();
    float m = mean_s, r = rstd_s;
    float* yr = y + (size_t)b * 2048;
#pragma unroll
    for (int i = 0; i < 8; i++) {
        int j = tid + 256 * i;
        yr[j] = rtf((v[i] - m) * r * w[j] + bb[j]);
    }
}

// ---------------- Attention (S=2, H=16, NH=64), writes concat layout -------
__global__ void attn_kernel(const float* __restrict__ Q, const float* __restrict__ K,
                            const float* __restrict__ V, float* __restrict__ O) {
    int b = blockIdx.x;
    int tid = threadIdx.x;
    __shared__ float sQ[2048], sK[2048];
    __shared__ float part[256 * 4];
    __shared__ float sp[4 * 16];    // [(s*2+t)*16 + h]
    const float* qp = Q + (size_t)b * 2048;
    const float* kp = K + (size_t)b * 2048;
#pragma unroll
    for (int i = 0; i < 8; i++) {
        sQ[tid + 256 * i] = qp[tid + 256 * i];
        sK[tid + 256 * i] = kp[tid + 256 * i];
    }
    __syncthreads();
    int h = tid & 15, u = tid >> 4;
    float p00 = 0.f, p01 = 0.f, p10 = 0.f, p11 = 0.f;
#pragma unroll
    for (int i = 0; i < 4; i++) {
        int j = h + 16 * u + 256 * i;     // columns with j%16 == h
        float q0 = sQ[j], q1 = sQ[1024 + j];
        float k0 = sK[j], k1 = sK[1024 + j];
        p00 += q0 * k0; p01 += q0 * k1;
        p10 += q1 * k0; p11 += q1 * k1;
    }
    part[tid * 4 + 0] = p00; part[tid * 4 + 1] = p01;
    part[tid * 4 + 2] = p10; part[tid * 4 + 3] = p11;
    __syncthreads();
    if (tid < 32) {
        int s = tid >> 4;
        int hh = tid & 15;
        float a0 = 0.f, a1 = 0.f;
#pragma unroll
        for (int uu = 0; uu < 16; uu++) {
            a0 += part[(uu * 16 + hh) * 4 + s * 2 + 0];
            a1 += part[(uu * 16 + hh) * 4 + s * 2 + 1];
        }
        a0 *= 0.125f; a1 *= 0.125f;           // / sqrt(64)
        float mx = fmaxf(a0, a1);
        float e0 = expf(a0 - mx), e1 = expf(a1 - mx);
        float inv = 1.f / (e0 + e1);
        sp[(s * 2 + 0) * 16 + hh] = e0 * inv;
        sp[(s * 2 + 1) * 16 + hh] = e1 * inv;
    }
    __syncthreads();
    const float* vp = V + (size_t)b * 2048;
    float* op = O + (size_t)b * 2048;
#pragma unroll
    for (int i = 0; i < 4; i++) {
        int j = tid + 256 * i;
        int hh = j & 15;
        float v0 = vp[j], v1 = vp[1024 + j];
        op[j]        = rtf(sp[0 * 16 + hh] * v0 + sp[1 * 16 + hh] * v1);
        op[1024 + j] = rtf(sp[2 * 16 + hh] * v0 + sp[3 * 16 + hh] * v1);
    }
}

// ---------------- TF32 tensor-core GEMM: C[m,n] = sum_k A[m,k]*W[n,k] -------
// All operands are PRE-ROUNDED to tf32 bit patterns; inner loop is LDS+MMA only.
#define BM 128
#define BN 128
#define BK 32
#define SROW 36                        // row stride in floats: conflict-free frag loads
#define STAGE_F (BM * SROW)            // 4608 floats / tile / stage
#define SMEM_BYTES (4 * STAGE_F * 4)   // A(2 stages) + B(2 stages) = 73728 B

__device__ __forceinline__ void cpa16(float* sdst, const float* g) {
    uint32_t s = (uint32_t)__cvta_generic_to_shared(sdst);
    asm volatile("cp.async.cg.shared.global [%0], [%1], 16;\n" :: "r"(s), "l"(g));
}
__device__ __forceinline__ void mma8(float* d, const uint32_t* a, const uint32_t* b2) {
    asm volatile(
        "mma.sync.aligned.m16n8k8.row.col.f32.tf32.tf32.f32 "
        "{%0,%1,%2,%3}, {%4,%5,%6,%7}, {%8,%9}, {%0,%1,%2,%3};\n"
        : "+f"(d[0]), "+f"(d[1]), "+f"(d[2]), "+f"(d[3])
        : "r"(a[0]), "r"(a[1]), "r"(a[2]), "r"(a[3]), "r"(b2[0]), "r"(b2[1]));
}

__global__ __launch_bounds__(256, 2) void gemm_tf32(
    const float* __restrict__ A, long lda,        // M x K (row-major)
    const float* __restrict__ W, long ldw,        // N x K (row-major)
    const float* __restrict__ bias,               // [N] or null
    const float* __restrict__ resid, long ldr,    // residual add or null
    float* __restrict__ C, long ldc,
    int K, int doTanh, int roundOut)
{
    extern __shared__ float smem[];
    float* sA = smem;                  // [2][BM][SROW]
    float* sB = smem + 2 * STAGE_F;    // [2][BN][SROW]
    int tid = threadIdx.x;
    int warp = tid >> 5, lane = tid & 31;
    int wm = warp >> 2, wn = warp & 3;             // warp grid 2(M) x 4(N), warp tile 64x32
    long bm = (long)blockIdx.y * BM;
    long bn = (long)blockIdx.x * BN;
    int lrow = tid >> 3;                            // 0..31
    int lcol = (tid & 7) * 4;                       // 0..28
    const float* Abase = A + (bm + lrow) * lda + lcol;
    const float* Wbase = W + (bn + lrow) * ldw + lcol;

    float acc[4][4][4];
#pragma unroll
    for (int i = 0; i < 4; i++)
#pragma unroll
        for (int j = 0; j < 4; j++)
#pragma unroll
            for (int q = 0; q < 4; q++) acc[i][j][q] = 0.f;

    int rA = wm * 64 + (lane >> 2);
    int rB = wn * 32 + (lane >> 2);
    int cL = lane & 3;

    int nk = K / BK;
    {   // prologue: stage 0
#pragma unroll
        for (int i = 0; i < 4; i++) {
            cpa16(&sA[(lrow + 32 * i) * SROW + lcol], Abase + (long)(32 * i) * lda);
            cpa16(&sB[(lrow + 32 * i) * SROW + lcol], Wbase + (long)(32 * i) * ldw);
        }
        asm volatile("cp.async.commit_group;\n");
    }
    for (int kt = 0; kt < nk; kt++) {
        if (kt + 1 < nk) {
            int stg = (kt + 1) & 1;
            float* dA = sA + stg * STAGE_F;
            float* dB = sB + stg * STAGE_F;
            long ko = (long)(kt + 1) * BK;
#pragma unroll
            for (int i = 0; i < 4; i++) {
                cpa16(&dA[(lrow + 32 * i) * SROW + lcol], Abase + (long)(32 * i) * lda + ko);
                cpa16(&dB[(lrow + 32 * i) * SROW + lcol], Wbase + (long)(32 * i) * ldw + ko);
            }
        }
        asm volatile("cp.async.commit_group;\n");
        asm volatile("cp.async.wait_group 1;\n");
        __syncthreads();
        const uint32_t* aS = (const uint32_t*)(sA + (kt & 1) * STAGE_F);
        const uint32_t* bS = (const uint32_t*)(sB + (kt & 1) * STAGE_F);
#pragma unroll
        for (int kk = 0; kk < BK; kk += 8) {
            uint32_t af[4][4], bf[4][2];
#pragma unroll
            for (int mt = 0; mt < 4; mt++) {
                const uint32_t* p = aS + (rA + mt * 16) * SROW + kk + cL;
                af[mt][0] = p[0];
                af[mt][1] = p[8 * SROW];
                af[mt][2] = p[4];
                af[mt][3] = p[8 * SROW + 4];
            }
#pragma unroll
            for (int nt = 0; nt < 4; nt++) {
                const uint32_t* p = bS + (rB + nt * 8) * SROW + kk + cL;
                bf[nt][0] = p[0];
                bf[nt][1] = p[4];
            }
#pragma unroll
            for (int mt = 0; mt < 4; mt++)
#pragma unroll
                for (int nt = 0; nt < 4; nt++)
                    mma8(acc[mt][nt], af[mt], bf[nt]);
        }
        __syncthreads();
    }
    // epilogue: bias -> tanh -> residual -> (optional tf32 round)
#pragma unroll
    for (int mt = 0; mt < 4; mt++) {
        long row0 = bm + wm * 64 + mt * 16 + (lane >> 2);
#pragma unroll
        for (int nt = 0; nt < 4; nt++) {
            long col = bn + wn * 32 + nt * 8 + (lane & 3) * 2;
#pragma unroll
            for (int hh = 0; hh < 2; hh++) {
                long row = row0 + hh * 8;
                float x0 = acc[mt][nt][hh * 2 + 0];
                float x1 = acc[mt][nt][hh * 2 + 1];
                if (bias) { x0 += bias[col]; x1 += bias[col + 1]; }
                if (doTanh) { x0 = tanhf(x0); x1 = tanhf(x1); }
                if (resid) {
                    const float* rp = resid + row * ldr + col;
                    x0 += rp[0]; x1 += rp[1];
                }
                if (roundOut) { x0 = rtf(x0); x1 = rtf(x1); }
                float2 o; o.x = x0; o.y = x1;
                *reinterpret_cast<float2*>(C + row * ldc + col) = o;
            }
        }
    }
}

// ---------------- host launch ------------------------------------------------
static float* symaddr(const void* s) {
    void* p = nullptr;
    cudaGetSymbolAddress(&p, s);
    return (float*)p;
}

extern "C" void kernel_launch(void* const* d_in, const int* in_sizes, int n_in,
                              void* d_out, int out_size) {
    const float* input = (const float*)d_in[0];
    const float* Wq    = (const float*)d_in[1];
    const float* Wk    = (const float*)d_in[2];
    const float* Wv    = (const float*)d_in[3];
    const float* Wo    = (const float*)d_in[4];
    const float* ln1w  = (const float*)d_in[5];
    const float* ln1b  = (const float*)d_in[6];
    const float* ln2w  = (const float*)d_in[7];
    const float* ln2b  = (const float*)d_in[8];
    const float* f1w1  = (const float*)d_in[9];
    const float* f1b1  = (const float*)d_in[10];
    const float* f1w2  = (const float*)d_in[11];
    const float* f1b2  = (const float*)d_in[12];
    const float* f2w1  = (const float*)d_in[13];
    const float* f2b1  = (const float*)d_in[14];
    const float* f2w2  = (const float*)d_in[15];
    const float* f2b2  = (const float*)d_in[16];
    float* out = (float*)d_out;

    float* xs = symaddr(g_xs);
    float* q  = symaddr(g_q);
    float* k  = symaddr(g_k);
    float* v  = symaddr(g_v);
    float* cc = symaddr(g_cc);
    float* o1 = symaddr(g_o1);
    float* os = symaddr(g_os);
    float* hd = symaddr(g_h);
    float* wr = symaddr(g_wr);

    const size_t M1 = 1024 * 1024;
    float* rWq   = wr;
    float* rWk   = wr + 1 * M1;
    float* rWv   = wr + 2 * M1;
    float* rWo   = wr + 3 * M1;
    float* rf1w1 = wr + 4 * M1;   // 2M
    float* rf1w2 = wr + 6 * M1;   // 2M
    float* rf2w1 = wr + 8 * M1;   // 2M
    float* rf2w2 = wr + 10 * M1;  // 2M

    cudaFuncSetAttribute(gemm_tf32, cudaFuncAttributeMaxDynamicSharedMemorySize, SMEM_BYTES);

    // 0) round all weights to tf32 once per replay
    round_w<<<(int)(M1 / 1024), 1024>>>(Wq, rWq, (int)M1);
    round_w<<<(int)(M1 / 1024), 1024>>>(Wk, rWk, (int)M1);
    round_w<<<(int)(M1 / 1024), 1024>>>(Wv, rWv, (int)M1);
    round_w<<<(int)(M1 / 1024), 1024>>>(Wo, rWo, (int)M1);
    round_w<<<(int)(2 * M1 / 1024), 1024>>>(f1w1, rf1w1, (int)(2 * M1));
    round_w<<<(int)(2 * M1 / 1024), 1024>>>(f1w2, rf1w2, (int)(2 * M1));
    round_w<<<(int)(2 * M1 / 1024), 1024>>>(f2w1, rf2w1, (int)(2 * M1));
    round_w<<<(int)(2 * M1 / 1024), 1024>>>(f2w2, rf2w2, (int)(2 * M1));

    // 1) LN1 (output tf32-rounded)
    ln_kernel<<<B_DIM, 256>>>(input, ln1w, ln1b, xs);

    // 2) Q/K/V projections
    dim3 gq(E_DIM / BN, NROWS / BM);   // (8, 128)
    gemm_tf32<<<gq, 256, SMEM_BYTES>>>(xs, E_DIM, rWq, E_DIM, nullptr, nullptr, 0, q, E_DIM, E_DIM, 0, 0);
    gemm_tf32<<<gq, 256, SMEM_BYTES>>>(xs, E_DIM, rWk, E_DIM, nullptr, nullptr, 0, k, E_DIM, E_DIM, 0, 0);
    gemm_tf32<<<gq, 256, SMEM_BYTES>>>(xs, E_DIM, rWv, E_DIM, nullptr, nullptr, 0, v, E_DIM, E_DIM, 0, 0);

    // 3) attention -> concat (output tf32-rounded)
    attn_kernel<<<B_DIM, 256>>>(q, k, v, cc);

    // 4) Wo projection, fused residual: o1 = input + concat @ Wo^T (full fp32 out)
    gemm_tf32<<<gq, 256, SMEM_BYTES>>>(cc, E_DIM, rWo, E_DIM, nullptr, input, E_DIM, o1, E_DIM, E_DIM, 0, 0);

    // 5) LN2 (output tf32-rounded)
    ln_kernel<<<B_DIM, 256>>>(o1, ln2w, ln2b, os);

    // 6) FFN s=0
    dim3 gf1(HID / BN, B_DIM / BM);    // (16, 64)
    dim3 gf2(E_DIM / BN, B_DIM / BM);  // (8, 64)
    gemm_tf32<<<gf1, 256, SMEM_BYTES>>>(os,        HID, rf1w1, E_DIM, f1b1, nullptr, 0,   hd,  HID,  E_DIM, 1, 1);
    gemm_tf32<<<gf2, 256, SMEM_BYTES>>>(hd,        HID, rf1w2, HID,   f1b2, o1,      HID, out, HID,  HID,   1, 0);
    // 7) FFN s=1
    gemm_tf32<<<gf1, 256, SMEM_BYTES>>>(os + 1024, HID, rf2w1, E_DIM, f2b1, nullptr, 0,   hd,        HID, E_DIM, 1, 1);
    gemm_tf32<<<gf2, 256, SMEM_BYTES>>>(hd,        HID, rf2w2, HID,   f2b2, o1 + 1024, HID, out + 1024, HID, HID, 1, 0);
}